// round 4
// baseline (speedup 1.0000x reference)
#include <cuda_runtime.h>
#include <cstdint>

// Haar DWT2: in [B=8, C=32, H=512, W=512] f32 -> out [B, 4, C, 256, 256] f32
// Subband order: LL, LH, HL, HH (pywt dwt2 'haar').
//
// Each thread: reads 8 consecutive rows x 4 cols (8x LDG.128, each warp
// instruction fully contiguous 512B, front-batched -> MLP_p1 = 8),
// producing 4 output rows x 2 cols per subband (16x STG.64, each warp
// instruction contiguous 256B).

#define B_  8
#define C_  32
#define H_  512
#define W_  512
#define H2 (H_/2)
#define W2 (W_/2)

__global__ void __launch_bounds__(256) haar_dwt2_kernel(
    const float* __restrict__ in, float* __restrict__ out)
{
    // total threads = B*C*(H2/4)*(W2/2) = 8*32*64*128 = 2,097,152
    const int64_t tid = (int64_t)blockIdx.x * blockDim.x + threadIdx.x;

    const int wpair = (int)(tid & (W2/2 - 1));           // 0..127 (2 output cols)
    const int ho    = (int)((tid >> 7) & (H2/4 - 1));    // 0..63  (4 output rows)
    const int bc    = (int)(tid >> 13);                  // 0..255 (b*32 + c)
    const int b     = bc >> 5;
    const int c     = bc & 31;

    // Input: rows 8*ho .. 8*ho+7, cols 4*wpair .. 4*wpair+3
    const int64_t in_base = ((int64_t)bc * H_ + 8 * ho) * W_ + 4 * wpair;
    float4 r[8];
    #pragma unroll
    for (int i = 0; i < 8; i++)
        r[i] = *reinterpret_cast<const float4*>(in + in_base + (int64_t)i * W_);

    // Output: [B, 4, C, H2, W2]
    const int64_t plane = (int64_t)H2 * W2;                        // 65536
    const int64_t sstride = (int64_t)C_ * plane;                   // subband stride
    const int64_t obase = (((int64_t)b * 4) * C_ + c) * plane
                          + (int64_t)(4 * ho) * W2 + 2 * wpair;

    #pragma unroll
    for (int p = 0; p < 4; p++) {
        const float4 t = r[2 * p];      // top row of pair
        const float4 u = r[2 * p + 1];  // bottom row of pair
        float2 LL, LH, HL, HH;
        LL.x = (t.x + t.y + u.x + u.y) * 0.5f;
        LH.x = (t.x + t.y - u.x - u.y) * 0.5f;
        HL.x = (t.x - t.y + u.x - u.y) * 0.5f;
        HH.x = (t.x - t.y - u.x + u.y) * 0.5f;
        LL.y = (t.z + t.w + u.z + u.w) * 0.5f;
        LH.y = (t.z + t.w - u.z - u.w) * 0.5f;
        HL.y = (t.z - t.w + u.z - u.w) * 0.5f;
        HH.y = (t.z - t.w - u.z + u.w) * 0.5f;

        const int64_t orow = obase + (int64_t)p * W2;
        *reinterpret_cast<float2*>(out + orow)               = LL;
        *reinterpret_cast<float2*>(out + orow + sstride)     = LH;
        *reinterpret_cast<float2*>(out + orow + 2 * sstride) = HL;
        *reinterpret_cast<float2*>(out + orow + 3 * sstride) = HH;
    }
}

extern "C" void kernel_launch(void* const* d_in, const int* in_sizes, int n_in,
                              void* d_out, int out_size)
{
    const float* in = (const float*)d_in[0];
    float* out = (float*)d_out;

    const int64_t total_threads = (int64_t)B_ * C_ * (H2/4) * (W2/2);  // 2,097,152
    const int threads = 256;
    const int blocks = (int)(total_threads / threads);                  // 8,192

    haar_dwt2_kernel<<<blocks, threads>>>(in, out);
}

// round 5
// speedup vs baseline: 1.0039x; 1.0039x over previous
#include <cuda_runtime.h>
#include <cstdint>

// Haar DWT2: in [B=8, C=32, H=512, W=512] f32 -> out [B, 4, C, 256, 256] f32
// Subband order: LL, LH, HL, HH (pywt dwt2 'haar').
//
// R3 tiling (4 rows x 4 cols per thread, fully coalesced per warp instruction)
// + streaming cache hints (__ldcs / __stcs; zero-reuse workload)
// + 512-thread blocks.

#define B_  8
#define C_  32
#define H_  512
#define W_  512
#define H2 (H_/2)
#define W2 (W_/2)

__global__ void __launch_bounds__(512) haar_dwt2_kernel(
    const float* __restrict__ in, float* __restrict__ out)
{
    // total threads = B*C*(H2/2)*(W2/2) = 8*32*128*128 = 4,194,304
    const int64_t tid = (int64_t)blockIdx.x * blockDim.x + threadIdx.x;

    const int wpair = (int)(tid & (W2/2 - 1));           // 0..127 (2 output cols)
    const int hq    = (int)((tid >> 7) & (H2/2 - 1));    // 0..127 (2 output rows)
    const int bc    = (int)(tid >> 14);                  // 0..255 (b*32 + c)
    const int b     = bc >> 5;
    const int c     = bc & 31;

    // Input: rows 4*hq .. 4*hq+3, cols 4*wpair .. 4*wpair+3
    const int64_t in_base = ((int64_t)bc * H_ + 4 * hq) * W_ + 4 * wpair;
    const float4 r0 = __ldcs(reinterpret_cast<const float4*>(in + in_base));
    const float4 r1 = __ldcs(reinterpret_cast<const float4*>(in + in_base + W_));
    const float4 r2 = __ldcs(reinterpret_cast<const float4*>(in + in_base + 2 * W_));
    const float4 r3 = __ldcs(reinterpret_cast<const float4*>(in + in_base + 3 * W_));

    // Output row 0 (h2 = 2*hq): from r0/r1
    float2 LL0, LH0, HL0, HH0;
    LL0.x = (r0.x + r0.y + r1.x + r1.y) * 0.5f;
    LH0.x = (r0.x + r0.y - r1.x - r1.y) * 0.5f;
    HL0.x = (r0.x - r0.y + r1.x - r1.y) * 0.5f;
    HH0.x = (r0.x - r0.y - r1.x + r1.y) * 0.5f;
    LL0.y = (r0.z + r0.w + r1.z + r1.w) * 0.5f;
    LH0.y = (r0.z + r0.w - r1.z - r1.w) * 0.5f;
    HL0.y = (r0.z - r0.w + r1.z - r1.w) * 0.5f;
    HH0.y = (r0.z - r0.w - r1.z + r1.w) * 0.5f;

    // Output row 1 (h2 = 2*hq+1): from r2/r3
    float2 LL1, LH1, HL1, HH1;
    LL1.x = (r2.x + r2.y + r3.x + r3.y) * 0.5f;
    LH1.x = (r2.x + r2.y - r3.x - r3.y) * 0.5f;
    HL1.x = (r2.x - r2.y + r3.x - r3.y) * 0.5f;
    HH1.x = (r2.x - r2.y - r3.x + r3.y) * 0.5f;
    LL1.y = (r2.z + r2.w + r3.z + r3.w) * 0.5f;
    LH1.y = (r2.z + r2.w - r3.z - r3.w) * 0.5f;
    HL1.y = (r2.z - r2.w + r3.z - r3.w) * 0.5f;
    HH1.y = (r2.z - r2.w - r3.z + r3.w) * 0.5f;

    // Output: [B, 4, C, H2, W2]
    const int64_t plane = (int64_t)H2 * W2;                        // 65536
    const int64_t obase = (((int64_t)b * 4) * C_ + c) * plane
                          + (int64_t)(2 * hq) * W2 + 2 * wpair;
    const int64_t sstride = (int64_t)C_ * plane;                   // subband stride

    __stcs(reinterpret_cast<float2*>(out + obase),                    LL0);
    __stcs(reinterpret_cast<float2*>(out + obase + W2),               LL1);
    __stcs(reinterpret_cast<float2*>(out + obase + sstride),          LH0);
    __stcs(reinterpret_cast<float2*>(out + obase + sstride + W2),     LH1);
    __stcs(reinterpret_cast<float2*>(out + obase + 2 * sstride),      HL0);
    __stcs(reinterpret_cast<float2*>(out + obase + 2 * sstride + W2), HL1);
    __stcs(reinterpret_cast<float2*>(out + obase + 3 * sstride),      HH0);
    __stcs(reinterpret_cast<float2*>(out + obase + 3 * sstride + W2), HH1);
}

extern "C" void kernel_launch(void* const* d_in, const int* in_sizes, int n_in,
                              void* d_out, int out_size)
{
    const float* in = (const float*)d_in[0];
    float* out = (float*)d_out;

    const int64_t total_threads = (int64_t)B_ * C_ * (H2/2) * (W2/2);  // 4,194,304
    const int threads = 512;
    const int blocks = (int)(total_threads / threads);                  // 8,192

    haar_dwt2_kernel<<<blocks, threads>>>(in, out);
}